// round 11
// baseline (speedup 1.0000x reference)
#include <cuda_runtime.h>
#include <cstdint>

#define HORIZON 30
#define INDIM   384
#define BMAX    65536

typedef unsigned long long ull;

// gi_base scratch, TRANSPOSED layout: [row = gate*256 + j][B] fp32 (192 MB).
__device__ float g_gi[(size_t)768 * BMAX];

__device__ __forceinline__ ull pack2(float lo, float hi) {
    ull r; asm("mov.b64 %0, {%1, %2};" : "=l"(r) : "f"(lo), "f"(hi)); return r;
}
__device__ __forceinline__ void ffma2(ull& d, ull a, ull b) {
    asm("fma.rn.f32x2 %0, %1, %2, %0;" : "+l"(d) : "l"(a), "l"(b));
}
__device__ __forceinline__ void unpack2(ull v, float& lo, float& hi) {
    asm("mov.b64 {%0, %1}, %2;" : "=f"(lo), "=f"(hi) : "l"(v));
}
__device__ __forceinline__ float sigf(float x) {
    return __fdividef(1.f, 1.f + __expf(-x));
}
__device__ __forceinline__ float tanh_fast(float x) {
    float t = __expf(2.f * x);
    return 1.f - __fdividef(2.f, t + 1.f);
}
__device__ __forceinline__ void cpa16(uint32_t s, const void* g) {
    asm volatile("cp.async.cg.shared.global [%0], [%1], 16;" :: "r"(s), "l"(g));
}
#define CPA_COMMIT() asm volatile("cp.async.commit_group;")
#define CPA_WAIT1()  asm volatile("cp.async.wait_group 1;")
#define CPA_WAIT0()  asm volatile("cp.async.wait_group 0;")

// ---------------- shared memory layout (floats) ----------------
#define HT_STRIDE 72
#define HT_SIZE   (256 * HT_STRIDE)          // 18432
#define OFF_HT    0                           // 2 ping-pong buffers
#define OFF_W     (2 * HT_SIZE)              // 36864
#define W_ROWPAD  20
#define WARP_WBUF (24 * W_ROWPAD)            // 480 floats
#define W_REGION  (16 * 2 * WARP_WBUF)       // 15360 floats
#define OFF_WMUX  (OFF_W + W_REGION)         // 52224
#define OFF_WMUY  (OFF_WMUX + 768)
#define OFF_BHH   (OFF_WMUY + 768)
#define OFF_W5    (OFF_BHH + 768)
#define OFF_MUX   (OFF_W5 + 1280)
#define OFF_MUY   (OFF_MUX + 64)
#define SMEM_FLOATS (OFF_MUY + 64)           // 55936 floats = 223744 B

#define NTHR 512

__device__ __forceinline__ int mgap(int m) { return m + ((m >> 5) << 2); }

// Per-warp private W staging (chunk c = jb*16 + kc; buffer index = c&1 = kc&1).
__device__ __forceinline__ void issue_chunk_w(uint32_t s_w_u32, const float* __restrict__ Whh,
                                              int c, int warp, int lane) {
    const int jb = (c >> 4) & 1;
    const int kc = c & 15;
    const uint32_t sbuf = s_w_u32 + (uint32_t)((warp * 2 + (c & 1)) * WARP_WBUF * 4);
    #pragma unroll
    for (int o = 0; o < 3; ++o) {
        int t = o * 32 + lane;            // 96 tasks: 24 rows x 4 quads
        int r = t >> 2, q = t & 3;
        int g = r >> 3, jj = r & 7;
        const float* gp = Whh + (size_t)(g * 256 + jb * 128 + warp * 8 + jj) * 256
                              + kc * 16 + q * 4;
        cpa16(sbuf + (uint32_t)((r * W_ROWPAD + q * 4) * 4), gp);
    }
}

__global__ void __launch_bounds__(NTHR, 1)
gru_decoder_kernel(const float* __restrict__ zh,  const float* __restrict__ Wh0,
                   const float* __restrict__ bh0, const float* __restrict__ Wih,
                   const float* __restrict__ bih, const float* __restrict__ Whh,
                   const float* __restrict__ bhhg,const float* __restrict__ Wmu,
                   const float* __restrict__ bmu, const float* __restrict__ Wcov,
                   const float* __restrict__ bcov,float* __restrict__ out, int B)
{
    extern __shared__ float sm[];
    float* s_w    = sm + OFF_W;
    float* s_wmux = sm + OFF_WMUX;
    float* s_wmuy = sm + OFF_WMUY;
    float* s_bhh  = sm + OFF_BHH;
    float* s_w5   = sm + OFF_W5;
    float* s_mux  = sm + OFF_MUX;
    float* s_muy  = sm + OFF_MUY;

    const int tid  = threadIdx.x;
    const int warp = tid >> 5, lane = tid & 31;
    const int wjb  = warp & 1;                // jb-stagger parity
    const int m0   = (lane & 7) * 8;
    const int m0p  = mgap(m0);
    const int jj0  = (lane >> 3) * 2;
    const int b0   = blockIdx.x * 64;
    const size_t Bs = (size_t)B;

    const uint32_t s_w_u32 = (uint32_t)__cvta_generic_to_shared(s_w);

    // ---- one-time small-weight staging ----
    for (int i = tid; i < 768; i += NTHR) {
        s_wmux[i] = Wih[(size_t)i * 386 + 384];
        s_wmuy[i] = Wih[(size_t)i * 386 + 385];
        s_bhh[i]  = bhhg[i];
    }
    for (int i = tid; i < 512; i += NTHR) s_w5[i] = Wmu[i];
    for (int i = tid; i < 768; i += NTHR) s_w5[512 + i] = Wcov[i];
    if (tid < 64) { s_mux[tid] = 0.f; s_muy[tid] = 0.f; }

    // ================= PRECOMPUTE: h0 (buf 0, gapped transposed) and gi_base ==========
    {
        const int tx4 = tid & 15, ty4 = tid >> 4;
        const int j04 = tx4 * 4, m04 = ty4 * 2;
        const int m04p = mgap(m04);
        float* s_zhT = s_w;          // [64 k][68]
        float* s_wtp = s_w + 4352;   // [64 k][68]

        for (int jb = 0; jb < 16; ++jb) {
            ull acc[2][2];
            acc[0][0]=0ull; acc[0][1]=0ull; acc[1][0]=0ull; acc[1][1]=0ull;

            for (int kc = 0; kc < 6; ++kc) {
                __syncthreads();
                #pragma unroll
                for (int it = 0; it < 8; ++it) {
                    int idx = it * NTHR + tid;
                    int kk = idx & 63, rr = idx >> 6;
                    s_zhT[kk * 68 + rr] = zh[(size_t)(b0 + rr) * INDIM + kc * 64 + kk];
                    int jp = jb * 64 + rr;
                    const float* wrow = (jp < 256) ? (Wh0 + (size_t)jp * 384)
                                                   : (Wih + (size_t)(jp - 256) * 386);
                    s_wtp[kk * 68 + rr] = wrow[kc * 64 + kk];
                }
                __syncthreads();
                #pragma unroll 8
                for (int k = 0; k < 64; ++k) {
                    float2 hv = *(const float2*)&s_zhT[k * 68 + m04];
                    ull w0 = *(const ull*)&s_wtp[k * 68 + j04];
                    ull w1 = *(const ull*)&s_wtp[k * 68 + j04 + 2];
                    ull a0 = pack2(hv.x, hv.x), a1 = pack2(hv.y, hv.y);
                    ffma2(acc[0][0], a0, w0); ffma2(acc[0][1], a0, w1);
                    ffma2(acc[1][0], a1, w0); ffma2(acc[1][1], a1, w1);
                }
            }
            float v[2][4];
            #pragma unroll
            for (int m = 0; m < 2; ++m) {
                unpack2(acc[m][0], v[m][0], v[m][1]);
                unpack2(acc[m][1], v[m][2], v[m][3]);
            }
            if (jb < 4) {
                #pragma unroll
                for (int jj = 0; jj < 4; ++jj) {
                    int j = jb * 64 + j04 + jj;
                    float b = bh0[j];
                    *(float2*)&sm[OFF_HT + (size_t)j * HT_STRIDE + m04p] =
                        make_float2(v[0][jj] + b, v[1][jj] + b);
                }
            } else {
                int gcol = jb * 64 - 256 + j04;
                float4 bb = *(const float4*)&bih[gcol];
                const float* bbp = (const float*)&bb;
                #pragma unroll
                for (int jj = 0; jj < 4; ++jj) {
                    *(float2*)&g_gi[(size_t)(gcol + jj) * Bs + b0 + m04] =
                        make_float2(v[0][jj] + bbp[jj], v[1][jj] + bbp[jj]);
                }
            }
        }
        __syncthreads();    // precompute done before W staging reuses s_w
    }

    const size_t covbase = (size_t)B * HORIZON * 2;

    // Prime per-warp W pipeline with this warp's first two chunks (its own jb order)
    issue_chunk_w(s_w_u32, Whh, wjb * 16 + 0, warp, lane);
    CPA_COMMIT();
    issue_chunk_w(s_w_u32, Whh, wjb * 16 + 1, warp, lane);
    CPA_COMMIT();

    // ================= 30-step GRU recurrence =================
    // Step structure (mu/cov hidden under next step's mainloop):
    //   kc-loop(jb0) ; B2 (s_mux from prev step's mu/cov now safe) ; epilogue(jb0)
    //   kc-loop(jb1) ;                                               epilogue(jb1)
    //   B1 (hnxt complete) ; mu/cov -> s_mux
    int cur = 0;
    #pragma unroll 1
    for (int t = 0; t < HORIZON; ++t) {
        float* hcur = sm + OFF_HT + cur * HT_SIZE;
        float* hnxt = sm + OFF_HT + (1 - cur) * HT_SIZE;

        #pragma unroll 1
        for (int jbi = 0; jbi < 2; ++jbi) {
            const int jb  = jbi ^ wjb;                    // staggered jb order per warp
            const int jg0 = jb * 128 + warp * 8 + jj0;    // lane's j-pair

            ull acc[3][2][4];
            #pragma unroll
            for (int g = 0; g < 3; ++g)
                #pragma unroll
                for (int j2 = 0; j2 < 2; ++j2) {
                    float b = s_bhh[g * 256 + jg0 + j2];
                    ull bb = pack2(b, b);
                    #pragma unroll
                    for (int mp = 0; mp < 4; ++mp) acc[g][j2][mp] = bb;
                }

            #pragma unroll 1
            for (int kc = 0; kc < 16; ++kc) {
                CPA_WAIT1();   // sequence element (jbi*16+kc) resident in buffer (kc&1)

                const float* wb  = s_w + (warp * 2 + (kc & 1)) * WARP_WBUF;
                const float* hch = hcur + (size_t)(kc * 16) * HT_STRIDE + m0p;

                #pragma unroll
                for (int kg = 0; kg < 4; ++kg) {
                    float4 w4[3][2];
                    #pragma unroll
                    for (int g = 0; g < 3; ++g)
                        #pragma unroll
                        for (int j2 = 0; j2 < 2; ++j2)
                            w4[g][j2] = *(const float4*)&wb[(g * 8 + jj0 + j2) * W_ROWPAD + kg * 4];
                    #pragma unroll
                    for (int kk = 0; kk < 4; ++kk) {
                        const float* hr = hch + (size_t)(kg * 4 + kk) * HT_STRIDE;
                        ulonglong2 q0 = *(const ulonglong2*)hr;
                        ulonglong2 q1 = *(const ulonglong2*)(hr + 4);
                        #pragma unroll
                        for (int g = 0; g < 3; ++g)
                            #pragma unroll
                            for (int j2 = 0; j2 < 2; ++j2) {
                                float ws = ((const float*)&w4[g][j2])[kk];
                                ull d = pack2(ws, ws);
                                ffma2(acc[g][j2][0], q0.x, d);
                                ffma2(acc[g][j2][1], q0.y, d);
                                ffma2(acc[g][j2][2], q1.x, d);
                                ffma2(acc[g][j2][3], q1.y, d);
                            }
                    }
                }
                // Issue sequence element s+2 (wraps into next step's identical order).
                {
                    int s2 = jbi * 16 + kc + 2;                 // up to 33
                    int jb2 = ((s2 >> 4) & 1) ^ wjb;
                    int c2  = jb2 * 16 + (s2 & 15);
                    issue_chunk_w(s_w_u32, Whh, c2, warp, lane);
                    CPA_COMMIT();
                }
            }

            // B2: first epilogue of this step needs s_mux/s_muy from previous
            // step's mu/cov (which overlapped with the kc-loop above).
            if (jbi == 0) __syncthreads();

            // ---- gate epilogue: per j2 to bound register pressure ----
            #pragma unroll
            for (int j2 = 0; j2 < 2; ++j2) {
                const int j = jg0 + j2;
                float fr[8], fz[8], fn[8];
                #pragma unroll
                for (int mp = 0; mp < 4; ++mp) {
                    unpack2(acc[0][j2][mp], fr[2*mp], fr[2*mp+1]);
                    unpack2(acc[1][j2][mp], fz[2*mp], fz[2*mp+1]);
                    unpack2(acc[2][j2][mp], fn[2*mp], fn[2*mp+1]);
                }
                const float* pr = g_gi + (size_t)(        j) * Bs + b0 + m0;
                const float* pz = g_gi + (size_t)(256 +   j) * Bs + b0 + m0;
                const float* pn = g_gi + (size_t)(512 +   j) * Bs + b0 + m0;
                float4 gr0 = *(const float4*)pr,       gr1 = *(const float4*)(pr + 4);
                float4 gz0 = *(const float4*)pz,       gz1 = *(const float4*)(pz + 4);
                float4 gn0 = *(const float4*)pn,       gn1 = *(const float4*)(pn + 4);
                float gR[8] = {gr0.x,gr0.y,gr0.z,gr0.w, gr1.x,gr1.y,gr1.z,gr1.w};
                float gZ[8] = {gz0.x,gz0.y,gz0.z,gz0.w, gz1.x,gz1.y,gz1.z,gz1.w};
                float gN[8] = {gn0.x,gn0.y,gn0.z,gn0.w, gn1.x,gn1.y,gn1.z,gn1.w};

                float wxr = s_wmux[j], wxz = s_wmux[256 + j], wxn = s_wmux[512 + j];
                float wyr = s_wmuy[j], wyz = s_wmuy[256 + j], wyn = s_wmuy[512 + j];

                const float* hp = &hcur[(size_t)j * HT_STRIDE + m0p];
                float4 o0 = *(const float4*)hp;
                float4 o1 = *(const float4*)(hp + 4);
                float ho[8] = {o0.x,o0.y,o0.z,o0.w,o1.x,o1.y,o1.z,o1.w};

                float hnew[8];
                #pragma unroll
                for (int m = 0; m < 8; ++m) {
                    float mx = s_mux[m0 + m], my = s_muy[m0 + m];
                    float r  = sigf(gR[m] + mx * wxr + my * wyr + fr[m]);
                    float z  = sigf(gZ[m] + mx * wxz + my * wyz + fz[m]);
                    float n  = tanh_fast(gN[m] + mx * wxn + my * wyn + r * fn[m]);
                    hnew[m] = (1.f - z) * n + z * ho[m];
                }
                float* hq = &hnxt[(size_t)j * HT_STRIDE + m0p];
                *(float4*)hq       = make_float4(hnew[0], hnew[1], hnew[2], hnew[3]);
                *(float4*)(hq + 4) = make_float4(hnew[4], hnew[5], hnew[6], hnew[7]);
            }
        } // jbi

        __syncthreads();   // B1: hnxt complete (both jb halves, all warps)

        // ---- mu / cov: 5 outputs x 32 m-pairs = 160 tasks, float2 column loads ----
        // Runs while the other warps proceed into the next step's kc-loop; the
        // s_mux consumers are fenced by B2 inside the next step.
        if (tid < 160) {
            int o = tid >> 5; int mp = tid & 31;
            int m = mp * 2;
            const float* wrow = &s_w5[o * 256];
            const float* hc = hnxt + mgap(m);
            float2 A0 = make_float2(0.f, 0.f), A1 = make_float2(0.f, 0.f);
            float2 A2 = make_float2(0.f, 0.f), A3 = make_float2(0.f, 0.f);
            #pragma unroll 4
            for (int k = 0; k < 256; k += 4) {
                float2 v0 = *(const float2*)&hc[(size_t)(k    ) * HT_STRIDE];
                float2 v1 = *(const float2*)&hc[(size_t)(k + 1) * HT_STRIDE];
                float2 v2 = *(const float2*)&hc[(size_t)(k + 2) * HT_STRIDE];
                float2 v3 = *(const float2*)&hc[(size_t)(k + 3) * HT_STRIDE];
                A0.x += v0.x * wrow[k    ];  A0.y += v0.y * wrow[k    ];
                A1.x += v1.x * wrow[k + 1];  A1.y += v1.y * wrow[k + 1];
                A2.x += v2.x * wrow[k + 2];  A2.y += v2.y * wrow[k + 2];
                A3.x += v3.x * wrow[k + 3];  A3.y += v3.y * wrow[k + 3];
            }
            float accA = (A0.x + A1.x) + (A2.x + A3.x);
            float accB = (A0.y + A1.y) + (A2.y + A3.y);
            #pragma unroll
            for (int h2 = 0; h2 < 2; ++h2) {
                float acc5 = h2 ? accB : accA;
                int mm = m + h2;
                size_t idx2 = ((size_t)(b0 + mm) * HORIZON + t);
                if (o == 0) {
                    float vv = acc5 + bmu[0]; out[idx2 * 2]     = vv; s_mux[mm] = vv;
                } else if (o == 1) {
                    float vv = acc5 + bmu[1]; out[idx2 * 2 + 1] = vv; s_muy[mm] = vv;
                } else if (o == 2) {
                    float vv = fminf(fmaxf(acc5 + bcov[0], 0.2f), 1.0f);
                    out[covbase + idx2 * 4]     = vv;
                } else if (o == 3) {
                    float vv = fminf(fmaxf(acc5 + bcov[1], -0.1f), 0.1f);
                    out[covbase + idx2 * 4 + 1] = vv;
                    out[covbase + idx2 * 4 + 2] = vv;
                } else {
                    float vv = fminf(fmaxf(acc5 + bcov[2], 0.2f), 1.0f);
                    out[covbase + idx2 * 4 + 3] = vv;
                }
            }
        }
        cur ^= 1;
        // no barrier here: next step's B2 (after its first kc-loop) fences s_mux.
    }

    CPA_WAIT0();   // drain speculative prefetches
}

extern "C" void kernel_launch(void* const* d_in, const int* in_sizes, int n_in,
                              void* d_out, int out_size) {
    const float* zh   = (const float*)d_in[0];
    const float* Wh0  = (const float*)d_in[1];
    const float* bh0  = (const float*)d_in[2];
    const float* Wih  = (const float*)d_in[3];
    const float* bih  = (const float*)d_in[4];
    const float* Whh  = (const float*)d_in[5];
    const float* bhh  = (const float*)d_in[6];
    const float* Wmu  = (const float*)d_in[7];
    const float* bmu  = (const float*)d_in[8];
    const float* Wcov = (const float*)d_in[9];
    const float* bcov = (const float*)d_in[10];
    float* out = (float*)d_out;

    int B = in_sizes[0] / INDIM;
    cudaFuncSetAttribute(gru_decoder_kernel,
                         cudaFuncAttributeMaxDynamicSharedMemorySize, SMEM_FLOATS * 4);
    gru_decoder_kernel<<<B / 64, NTHR, SMEM_FLOATS * 4>>>(
        zh, Wh0, bh0, Wih, bih, Whh, bhh, Wmu, bmu, Wcov, bcov, out, B);
}

// round 12
// speedup vs baseline: 1.0739x; 1.0739x over previous
#include <cuda_runtime.h>
#include <cstdint>

#define HORIZON 30
#define INDIM   384
#define BMAX    65536

typedef unsigned long long ull;

// gi_base scratch, TRANSPOSED layout: [row = gate*256 + j][B] fp32 (192 MB).
__device__ float g_gi[(size_t)768 * BMAX];

__device__ __forceinline__ ull pack2(float lo, float hi) {
    ull r; asm("mov.b64 %0, {%1, %2};" : "=l"(r) : "f"(lo), "f"(hi)); return r;
}
__device__ __forceinline__ void ffma2(ull& d, ull a, ull b) {
    asm("fma.rn.f32x2 %0, %1, %2, %0;" : "+l"(d) : "l"(a), "l"(b));
}
__device__ __forceinline__ void unpack2(ull v, float& lo, float& hi) {
    asm("mov.b64 {%0, %1}, %2;" : "=f"(lo), "=f"(hi) : "l"(v));
}
__device__ __forceinline__ float sigf(float x) {
    return __fdividef(1.f, 1.f + __expf(-x));
}
__device__ __forceinline__ float tanh_fast(float x) {
    float t = __expf(2.f * x);
    return 1.f - __fdividef(2.f, t + 1.f);
}
__device__ __forceinline__ void cpa16(uint32_t s, const void* g) {
    asm volatile("cp.async.cg.shared.global [%0], [%1], 16;" :: "r"(s), "l"(g));
}
#define CPA_COMMIT() asm volatile("cp.async.commit_group;")
#define CPA_WAIT1()  asm volatile("cp.async.wait_group 1;")
#define CPA_WAIT0()  asm volatile("cp.async.wait_group 0;")

// ---------------- shared memory layout (floats) ----------------
#define HT_STRIDE 72
#define HT_SIZE   (256 * HT_STRIDE)          // 18432
#define OFF_HT    0                           // 2 ping-pong buffers
#define OFF_W     (2 * HT_SIZE)              // 36864
#define W_ROWPAD  20
#define WARP_WBUF (48 * W_ROWPAD)            // 960 floats: 48 rows x 16 k
#define W_REGION  (8 * 2 * WARP_WBUF)        // 15360 floats (8 warps x 2 buffers)
#define OFF_WMUX  (OFF_W + W_REGION)         // 52224
#define OFF_WMUY  (OFF_WMUX + 768)
#define OFF_BHH   (OFF_WMUY + 768)
#define OFF_W5    (OFF_BHH + 768)
#define OFF_MUX   (OFF_W5 + 1280)
#define OFF_MUY   (OFF_MUX + 64)
#define SMEM_FLOATS (OFF_MUY + 64)           // 55936 floats = 223744 B

#define NTHR 256

__device__ __forceinline__ int mgap(int m) { return m + ((m >> 5) << 2); }

// Per-warp private W staging. Warp owns 16 j per jb (x3 gates = 48 rows).
// Buffer row layout (PERMUTED for conflict-free compute reads):
//   row = g*16 + j2*4 + grp   holds Whh row (g*256 + jb*128 + warp*16 + grp*4 + j2)
// Compute read for (g, j2) at lane-group grp: rows stride 1 -> 20 floats ->
// quads hit banks [0-3],[20-23],[8-11],[28-31]: conflict-free.
__device__ __forceinline__ void issue_chunk_w(uint32_t s_w_u32, const float* __restrict__ Whh,
                                              int c, int warp, int lane) {
    const int jb = (c >> 4) & 1;
    const int kc = c & 15;
    const uint32_t sbuf = s_w_u32 + (uint32_t)((warp * 2 + (c & 1)) * WARP_WBUF * 4);
    #pragma unroll
    for (int o = 0; o < 6; ++o) {
        int t = o * 32 + lane;            // 192 tasks: 48 rows x 4 quads
        int r = t >> 2, q = t & 3;        // r: buffer row 0..47
        int g = r >> 4, rl = r & 15;
        int jloc = (rl & 3) * 4 + (rl >> 2);   // inverse of row permutation
        const float* gp = Whh + (size_t)(g * 256 + jb * 128 + warp * 16 + jloc) * 256
                              + kc * 16 + q * 4;
        cpa16(sbuf + (uint32_t)((r * W_ROWPAD + q * 4) * 4), gp);
    }
}

__global__ void __launch_bounds__(NTHR, 1)
gru_decoder_kernel(const float* __restrict__ zh,  const float* __restrict__ Wh0,
                   const float* __restrict__ bh0, const float* __restrict__ Wih,
                   const float* __restrict__ bih, const float* __restrict__ Whh,
                   const float* __restrict__ bhhg,const float* __restrict__ Wmu,
                   const float* __restrict__ bmu, const float* __restrict__ Wcov,
                   const float* __restrict__ bcov,float* __restrict__ out, int B)
{
    extern __shared__ float sm[];
    float* s_w    = sm + OFF_W;
    float* s_wmux = sm + OFF_WMUX;
    float* s_wmuy = sm + OFF_WMUY;
    float* s_bhh  = sm + OFF_BHH;
    float* s_w5   = sm + OFF_W5;
    float* s_mux  = sm + OFF_MUX;
    float* s_muy  = sm + OFF_MUY;

    const int tid  = threadIdx.x;
    const int warp = tid >> 5, lane = tid & 31;
    const int wjb  = warp & 1;                // jb-stagger parity
    const int grp  = lane >> 3;               // 0..3: j-group within warp slice
    const int m0   = (lane & 7) * 8;          // 8 batch rows (4 f32x2 pairs)
    const int m0p  = mgap(m0);
    const int b0   = blockIdx.x * 64;
    const size_t Bs = (size_t)B;

    const uint32_t s_w_u32 = (uint32_t)__cvta_generic_to_shared(s_w);

    // ---- one-time small-weight staging ----
    for (int i = tid; i < 768; i += NTHR) {
        s_wmux[i] = Wih[(size_t)i * 386 + 384];
        s_wmuy[i] = Wih[(size_t)i * 386 + 385];
        s_bhh[i]  = bhhg[i];
    }
    for (int i = tid; i < 512; i += NTHR) s_w5[i] = Wmu[i];
    for (int i = tid; i < 768; i += NTHR) s_w5[512 + i] = Wcov[i];
    if (tid < 64) { s_mux[tid] = 0.f; s_muy[tid] = 0.f; }

    // ================= PRECOMPUTE: h0 (buf 0, gapped transposed) and gi_base ==========
    {
        const int tx4 = tid & 15, ty4 = tid >> 4;   // 16 x 16
        const int j04 = tx4 * 4, m04 = ty4 * 4;     // j-tile 4, m-tile 4
        const int m04p = mgap(m04);                  // m04 mult of 4: no gap crossing
        float* s_zhT = s_w;          // [64 k][68]
        float* s_wtp = s_w + 4352;   // [64 k][68]

        for (int jb = 0; jb < 16; ++jb) {
            ull acc[4][2];
            #pragma unroll
            for (int m = 0; m < 4; ++m) { acc[m][0] = 0ull; acc[m][1] = 0ull; }

            for (int kc = 0; kc < 6; ++kc) {
                __syncthreads();
                #pragma unroll
                for (int it = 0; it < 16; ++it) {
                    int idx = it * NTHR + tid;
                    int kk = idx & 63, rr = idx >> 6;
                    s_zhT[kk * 68 + rr] = zh[(size_t)(b0 + rr) * INDIM + kc * 64 + kk];
                    int jp = jb * 64 + rr;
                    const float* wrow = (jp < 256) ? (Wh0 + (size_t)jp * 384)
                                                   : (Wih + (size_t)(jp - 256) * 386);
                    s_wtp[kk * 68 + rr] = wrow[kc * 64 + kk];
                }
                __syncthreads();
                #pragma unroll 8
                for (int k = 0; k < 64; ++k) {
                    float4 hv = *(const float4*)&s_zhT[k * 68 + m04];
                    ull w0 = *(const ull*)&s_wtp[k * 68 + j04];
                    ull w1 = *(const ull*)&s_wtp[k * 68 + j04 + 2];
                    ull a0 = pack2(hv.x, hv.x), a1 = pack2(hv.y, hv.y);
                    ull a2 = pack2(hv.z, hv.z), a3 = pack2(hv.w, hv.w);
                    ffma2(acc[0][0], a0, w0); ffma2(acc[0][1], a0, w1);
                    ffma2(acc[1][0], a1, w0); ffma2(acc[1][1], a1, w1);
                    ffma2(acc[2][0], a2, w0); ffma2(acc[2][1], a2, w1);
                    ffma2(acc[3][0], a3, w0); ffma2(acc[3][1], a3, w1);
                }
            }
            float v[4][4];
            #pragma unroll
            for (int m = 0; m < 4; ++m) {
                unpack2(acc[m][0], v[m][0], v[m][1]);
                unpack2(acc[m][1], v[m][2], v[m][3]);
            }
            if (jb < 4) {
                #pragma unroll
                for (int jj = 0; jj < 4; ++jj) {
                    int j = jb * 64 + j04 + jj;
                    float b = bh0[j];
                    *(float4*)&sm[OFF_HT + (size_t)j * HT_STRIDE + m04p] =
                        make_float4(v[0][jj] + b, v[1][jj] + b, v[2][jj] + b, v[3][jj] + b);
                }
            } else {
                int gcol = jb * 64 - 256 + j04;
                float4 bb = *(const float4*)&bih[gcol];
                const float* bbp = (const float*)&bb;
                #pragma unroll
                for (int jj = 0; jj < 4; ++jj) {
                    *(float4*)&g_gi[(size_t)(gcol + jj) * Bs + b0 + m04] =
                        make_float4(v[0][jj] + bbp[jj], v[1][jj] + bbp[jj],
                                    v[2][jj] + bbp[jj], v[3][jj] + bbp[jj]);
                }
            }
        }
        __syncthreads();    // precompute done before W staging reuses s_w
    }

    const size_t covbase = (size_t)B * HORIZON * 2;

    // Prime per-warp W pipeline with this warp's first two chunks (its own jb order)
    issue_chunk_w(s_w_u32, Whh, wjb * 16 + 0, warp, lane);
    CPA_COMMIT();
    issue_chunk_w(s_w_u32, Whh, wjb * 16 + 1, warp, lane);
    CPA_COMMIT();

    // ================= 30-step GRU recurrence (R7 barrier scheme) =================
    int cur = 0;
    #pragma unroll 1
    for (int t = 0; t < HORIZON; ++t) {
        float* hcur = sm + OFF_HT + cur * HT_SIZE;
        float* hnxt = sm + OFF_HT + (1 - cur) * HT_SIZE;

        #pragma unroll 1
        for (int jbi = 0; jbi < 2; ++jbi) {
            const int jb  = jbi ^ wjb;                         // staggered jb order
            const int jg0 = jb * 128 + warp * 16 + grp * 4;    // lane's 4 contiguous j

            // acc[gate][j2][mpair], seeded with b_hh
            ull acc[3][4][4];
            #pragma unroll
            for (int g = 0; g < 3; ++g)
                #pragma unroll
                for (int j2 = 0; j2 < 4; ++j2) {
                    float b = s_bhh[g * 256 + jg0 + j2];
                    ull bb = pack2(b, b);
                    #pragma unroll
                    for (int mp = 0; mp < 4; ++mp) acc[g][j2][mp] = bb;
                }

            #pragma unroll 1
            for (int kc = 0; kc < 16; ++kc) {
                CPA_WAIT1();   // sequence element (jbi*16+kc) resident in buffer (kc&1)

                const float* wb  = s_w + (warp * 2 + (kc & 1)) * WARP_WBUF;
                const float* hch = hcur + (size_t)(kc * 16) * HT_STRIDE + m0p;

                #pragma unroll
                for (int kg = 0; kg < 4; ++kg) {
                    // 12 LDS.128: W quads for (3 gates x 4 j2), conflict-free rows
                    float4 w4[3][4];
                    #pragma unroll
                    for (int g = 0; g < 3; ++g)
                        #pragma unroll
                        for (int j2 = 0; j2 < 4; ++j2)
                            w4[g][j2] = *(const float4*)
                                &wb[(g * 16 + j2 * 4 + grp) * W_ROWPAD + kg * 4];
                    #pragma unroll
                    for (int kk = 0; kk < 4; ++kk) {
                        const float* hr = hch + (size_t)(kg * 4 + kk) * HT_STRIDE;
                        ulonglong2 q0 = *(const ulonglong2*)hr;        // m pairs 0..1
                        ulonglong2 q1 = *(const ulonglong2*)(hr + 4);  // m pairs 2..3
                        #pragma unroll
                        for (int g = 0; g < 3; ++g)
                            #pragma unroll
                            for (int j2 = 0; j2 < 4; ++j2) {
                                float ws = ((const float*)&w4[g][j2])[kk];
                                ull d = pack2(ws, ws);
                                ffma2(acc[g][j2][0], q0.x, d);
                                ffma2(acc[g][j2][1], q0.y, d);
                                ffma2(acc[g][j2][2], q1.x, d);
                                ffma2(acc[g][j2][3], q1.y, d);
                            }
                    }
                }
                // Issue sequence element s+2 (wraps into next step's identical order).
                {
                    int s2 = jbi * 16 + kc + 2;                 // up to 33
                    int jb2 = ((s2 >> 4) & 1) ^ wjb;
                    int c2  = jb2 * 16 + (s2 & 15);
                    issue_chunk_w(s_w_u32, Whh, c2, warp, lane);
                    CPA_COMMIT();
                }
            }

            // ---- gate epilogue: 4 j x 8 m GRU cells (per j2 to bound reg pressure) ----
            #pragma unroll
            for (int j2 = 0; j2 < 4; ++j2) {
                const int j = jg0 + j2;
                float fr[8], fz[8], fn[8];
                #pragma unroll
                for (int mp = 0; mp < 4; ++mp) {
                    unpack2(acc[0][j2][mp], fr[2*mp], fr[2*mp+1]);
                    unpack2(acc[1][j2][mp], fz[2*mp], fz[2*mp+1]);
                    unpack2(acc[2][j2][mp], fn[2*mp], fn[2*mp+1]);
                }
                const float* pr = g_gi + (size_t)(        j) * Bs + b0 + m0;
                const float* pz = g_gi + (size_t)(256 +   j) * Bs + b0 + m0;
                const float* pn = g_gi + (size_t)(512 +   j) * Bs + b0 + m0;
                float4 gr0 = *(const float4*)pr,       gr1 = *(const float4*)(pr + 4);
                float4 gz0 = *(const float4*)pz,       gz1 = *(const float4*)(pz + 4);
                float4 gn0 = *(const float4*)pn,       gn1 = *(const float4*)(pn + 4);
                float gR[8] = {gr0.x,gr0.y,gr0.z,gr0.w, gr1.x,gr1.y,gr1.z,gr1.w};
                float gZ[8] = {gz0.x,gz0.y,gz0.z,gz0.w, gz1.x,gz1.y,gz1.z,gz1.w};
                float gN[8] = {gn0.x,gn0.y,gn0.z,gn0.w, gn1.x,gn1.y,gn1.z,gn1.w};

                float wxr = s_wmux[j], wxz = s_wmux[256 + j], wxn = s_wmux[512 + j];
                float wyr = s_wmuy[j], wyz = s_wmuy[256 + j], wyn = s_wmuy[512 + j];

                const float* hp = &hcur[(size_t)j * HT_STRIDE + m0p];
                float4 o0 = *(const float4*)hp;
                float4 o1 = *(const float4*)(hp + 4);
                float ho[8] = {o0.x,o0.y,o0.z,o0.w,o1.x,o1.y,o1.z,o1.w};

                float hnew[8];
                #pragma unroll
                for (int m = 0; m < 8; ++m) {
                    float mx = s_mux[m0 + m], my = s_muy[m0 + m];
                    float r  = sigf(gR[m] + mx * wxr + my * wyr + fr[m]);
                    float z  = sigf(gZ[m] + mx * wxz + my * wyz + fz[m]);
                    float n  = tanh_fast(gN[m] + mx * wxn + my * wyn + r * fn[m]);
                    hnew[m] = (1.f - z) * n + z * ho[m];
                }
                float* hq = &hnxt[(size_t)j * HT_STRIDE + m0p];
                *(float4*)hq       = make_float4(hnew[0], hnew[1], hnew[2], hnew[3]);
                *(float4*)(hq + 4) = make_float4(hnew[4], hnew[5], hnew[6], hnew[7]);
            }
        } // jbi

        __syncthreads();   // hnxt complete (both jb halves, all warps)

        // ---- mu / cov: 5 outputs x 32 m-pairs = 160 tasks, float2 column loads ----
        if (tid < 160) {
            int o = tid >> 5; int mp = tid & 31;
            int m = mp * 2;
            const float* wrow = &s_w5[o * 256];
            const float* hc = hnxt + mgap(m);
            float2 A0 = make_float2(0.f, 0.f), A1 = make_float2(0.f, 0.f);
            float2 A2 = make_float2(0.f, 0.f), A3 = make_float2(0.f, 0.f);
            #pragma unroll 4
            for (int k = 0; k < 256; k += 4) {
                float2 v0 = *(const float2*)&hc[(size_t)(k    ) * HT_STRIDE];
                float2 v1 = *(const float2*)&hc[(size_t)(k + 1) * HT_STRIDE];
                float2 v2 = *(const float2*)&hc[(size_t)(k + 2) * HT_STRIDE];
                float2 v3 = *(const float2*)&hc[(size_t)(k + 3) * HT_STRIDE];
                A0.x += v0.x * wrow[k    ];  A0.y += v0.y * wrow[k    ];
                A1.x += v1.x * wrow[k + 1];  A1.y += v1.y * wrow[k + 1];
                A2.x += v2.x * wrow[k + 2];  A2.y += v2.y * wrow[k + 2];
                A3.x += v3.x * wrow[k + 3];  A3.y += v3.y * wrow[k + 3];
            }
            float accA = (A0.x + A1.x) + (A2.x + A3.x);
            float accB = (A0.y + A1.y) + (A2.y + A3.y);
            #pragma unroll
            for (int h2 = 0; h2 < 2; ++h2) {
                float acc5 = h2 ? accB : accA;
                int mm = m + h2;
                size_t idx2 = ((size_t)(b0 + mm) * HORIZON + t);
                if (o == 0) {
                    float vv = acc5 + bmu[0]; out[idx2 * 2]     = vv; s_mux[mm] = vv;
                } else if (o == 1) {
                    float vv = acc5 + bmu[1]; out[idx2 * 2 + 1] = vv; s_muy[mm] = vv;
                } else if (o == 2) {
                    float vv = fminf(fmaxf(acc5 + bcov[0], 0.2f), 1.0f);
                    out[covbase + idx2 * 4]     = vv;
                } else if (o == 3) {
                    float vv = fminf(fmaxf(acc5 + bcov[1], -0.1f), 0.1f);
                    out[covbase + idx2 * 4 + 1] = vv;
                    out[covbase + idx2 * 4 + 2] = vv;
                } else {
                    float vv = fminf(fmaxf(acc5 + bcov[2], 0.2f), 1.0f);
                    out[covbase + idx2 * 4 + 3] = vv;
                }
            }
        }
        __syncthreads();   // s_mux/s_muy published before next step's epilogues read
        cur ^= 1;
    }

    CPA_WAIT0();   // drain speculative prefetches
}

extern "C" void kernel_launch(void* const* d_in, const int* in_sizes, int n_in,
                              void* d_out, int out_size) {
    const float* zh   = (const float*)d_in[0];
    const float* Wh0  = (const float*)d_in[1];
    const float* bh0  = (const float*)d_in[2];
    const float* Wih  = (const float*)d_in[3];
    const float* bih  = (const float*)d_in[4];
    const float* Whh  = (const float*)d_in[5];
    const float* bhh  = (const float*)d_in[6];
    const float* Wmu  = (const float*)d_in[7];
    const float* bmu  = (const float*)d_in[8];
    const float* Wcov = (const float*)d_in[9];
    const float* bcov = (const float*)d_in[10];
    float* out = (float*)d_out;

    int B = in_sizes[0] / INDIM;
    cudaFuncSetAttribute(gru_decoder_kernel,
                         cudaFuncAttributeMaxDynamicSharedMemorySize, SMEM_FLOATS * 4);
    gru_decoder_kernel<<<B / 64, NTHR, SMEM_FLOATS * 4>>>(
        zh, Wh0, bh0, Wih, bih, Whh, bhh, Wmu, bmu, Wcov, bcov, out, B);
}